// round 10
// baseline (speedup 1.0000x reference)
#include <cuda_runtime.h>

#define N_NODES 50000
#define N_EDGES 800000
#define NODE_DIM 64
#define HIDDEN 128
#define OUT_DIM 256
#define N_LAYERS 3
#define ECAP 1024

typedef unsigned long long u64;

// Scratch (static device globals; zero-initialized at load; self-restoring)
__device__ float d_hbuf0[(size_t)N_NODES * HIDDEN];
__device__ float d_hbuf1[(size_t)N_NODES * HIDDEN];
__device__ float d_deg[N_NODES];      // 1/deg (0 for isolated nodes)
__device__ float d_gsum[HIDDEN];      // zeroed by scan_kernel each call
__device__ int   d_cnt[N_NODES];      // histogram; reset by scan_kernel
__device__ int   d_row[N_NODES + 1];  // CSR row offsets
__device__ int   d_cur[N_NODES];      // fill cursors
__device__ int   d_colA[N_EDGES];     // CSR columns (src per edge slot)

// ---- packed f32x2 helpers ---------------------------------------------------
__device__ __forceinline__ u64 pack2(float lo, float hi) {
    u64 r;
    asm("mov.b64 %0, {%1, %2};" : "=l"(r)
        : "r"(__float_as_uint(lo)), "r"(__float_as_uint(hi)));
    return r;
}
__device__ __forceinline__ void unpack2(u64 v, float& lo, float& hi) {
    unsigned int a, b;
    asm("mov.b64 {%0, %1}, %2;" : "=r"(a), "=r"(b) : "l"(v));
    lo = __uint_as_float(a);
    hi = __uint_as_float(b);
}
__device__ __forceinline__ void fma2(u64& acc, u64 a, u64 b) {
    asm("fma.rn.f32x2 %0, %1, %2, %0;" : "+l"(acc) : "l"(a), "l"(b));
}

// ---- cp.async helpers -------------------------------------------------------
__device__ __forceinline__ unsigned smem_u32(const void* p) {
    return (unsigned)__cvta_generic_to_shared(p);
}
__device__ __forceinline__ void cp_async16(unsigned saddr, const void* g) {
    asm volatile("cp.async.cg.shared.global [%0], [%1], 16;"
                 :: "r"(saddr), "l"(g) : "memory");
}
#define CP_COMMIT() asm volatile("cp.async.commit_group;" ::: "memory")
#define CP_WAIT1()  asm volatile("cp.async.wait_group 1;" ::: "memory")
#define CP_WAIT0()  asm volatile("cp.async.wait_group 0;" ::: "memory")

// ---------------------------------------------------------------------------
// launch 0: h0 = x @ Wp + bp
__global__ void __launch_bounds__(128) proj_kernel(const float* __restrict__ x,
                            const float* __restrict__ Wp,
                            const float* __restrict__ bp) {
    __shared__ float xs[32][NODE_DIM];
    int t = threadIdx.x;
    int node0 = blockIdx.x * 32;

    for (int i = t; i < 32 * (NODE_DIM / 4); i += 128) {
        int r = i >> 4;
        int c4 = i & 15;
        int node = node0 + r;
        float4 v = make_float4(0.f, 0.f, 0.f, 0.f);
        if (node < N_NODES)
            v = ((const float4*)(x + (size_t)node * NODE_DIM))[c4];
        *(float4*)&xs[r][c4 * 4] = v;
    }
    __syncthreads();

    int ct = t & 31;
    int nt = t >> 5;
    int colb = ct * 4;

    u64 acc2[8][2];
#pragma unroll
    for (int i = 0; i < 8; i++) { acc2[i][0] = 0ull; acc2[i][1] = 0ull; }

    const float4* W4 = (const float4*)Wp;
#pragma unroll 4
    for (int k = 0; k < NODE_DIM; k++) {
        float4 w = W4[k * 32 + ct];
        u64 wp0 = pack2(w.x, w.y);
        u64 wp1 = pack2(w.z, w.w);
#pragma unroll
        for (int i = 0; i < 8; i++) {
            float m = xs[nt * 8 + i][k];
            u64 mp = pack2(m, m);
            fma2(acc2[i][0], mp, wp0);
            fma2(acc2[i][1], mp, wp1);
        }
    }

    float4 bv = ((const float4*)bp)[ct];
#pragma unroll
    for (int i = 0; i < 8; i++) {
        int node = node0 + nt * 8 + i;
        if (node < N_NODES) {
            float4 r;
            unpack2(acc2[i][0], r.x, r.y);
            unpack2(acc2[i][1], r.z, r.w);
            r.x += bv.x; r.y += bv.y; r.z += bv.z; r.w += bv.w;
            *(float4*)(d_hbuf0 + (size_t)node * HIDDEN + colb) = r;
        }
    }
}

// ---------------------------------------------------------------------------
// launch 1: degree histogram
__global__ void hist_kernel(const int* __restrict__ dst) {
    int e = blockIdx.x * blockDim.x + threadIdx.x;
    if (e < N_EDGES) atomicAdd(&d_cnt[dst[e]], 1);
}

// ---------------------------------------------------------------------------
// launch 2: single-block scan -> row/cur/deg; resets cnt,gsum.
__global__ void __launch_bounds__(1024) scan_kernel() {
    const int PER = (N_NODES + 1023) / 1024;   // 49
    int t = threadIdx.x;
    int base = t * PER;

    int s = 0;
#pragma unroll 1
    for (int j = 0; j < PER; j++) {
        int i = base + j;
        if (i < N_NODES) s += d_cnt[i];
    }

    int lane = t & 31;
    int wid = t >> 5;
    int incl = s;
#pragma unroll
    for (int off = 1; off < 32; off <<= 1) {
        int v = __shfl_up_sync(0xffffffffu, incl, off);
        if (lane >= off) incl += v;
    }
    __shared__ int wsum[32];
    __shared__ int wpre[32];
    if (lane == 31) wsum[wid] = incl;
    __syncthreads();
    if (wid == 0) {
        int v = wsum[lane];
        int wincl = v;
#pragma unroll
        for (int off = 1; off < 32; off <<= 1) {
            int u2 = __shfl_up_sync(0xffffffffu, wincl, off);
            if (lane >= off) wincl += u2;
        }
        wpre[lane] = wincl - v;
    }
    __syncthreads();

    int run = wpre[wid] + incl - s;
#pragma unroll 1
    for (int j = 0; j < PER; j++) {
        int i = base + j;
        if (i < N_NODES) {
            int c = d_cnt[i];
            d_row[i] = run;
            d_cur[i] = run;
            d_deg[i] = c ? (1.0f / (float)c) : 0.0f;
            d_cnt[i] = 0;
            run += c;
        }
    }
    if (t == 0) d_row[N_NODES] = N_EDGES;
    if (t < HIDDEN) d_gsum[t] = 0.0f;
}

// ---------------------------------------------------------------------------
// launch 3: CSR column fill
__global__ void fill_kernel(const int* __restrict__ src, const int* __restrict__ dst) {
    int e = blockIdx.x * blockDim.x + threadIdx.x;
    if (e < N_EDGES) {
        int d = dst[e];
        int pos = atomicAdd(&d_cur[d], 1);
        d_colA[pos] = src[e];
    }
}

// ---------------------------------------------------------------------------
// launches 4..6: fused GNN layer: hout = relu(hin + gather_mean(hin) @ Wg + bg)
// Gather: cp.async.cg double-buffered staging (2 bufs x 4 edges x 512B per warp);
// same-lane produce/consume -> no barrier; loads have no register destination.
// GEMM: thread owns 8 nodes x 4 cols, packed fma2 (R4-proven).
__global__ void __launch_bounds__(128) layer_kernel(const float* __restrict__ hin,
                             float* __restrict__ hout,
                             const float* __restrict__ Wg,
                             const float* __restrict__ bg,
                             int do_reduce) {
    __shared__ float ms[32][HIDDEN];          // 16 KB
    __shared__ int sidx[ECAP];                // 4 KB
    __shared__ int srow[33];
    __shared__ float4 gbuf[4][2][4][32];      // [warp][buf][slot][lane] = 16 KB
    int t = threadIdx.x;
    int node0 = blockIdx.x * 32;
    int lane = t & 31;
    int w = t >> 5;   // warp 0..3

    if (t < 33) srow[t] = d_row[min(node0 + t, N_NODES)];
    __syncthreads();
    int ebase = srow[0];
    int etot = srow[32] - ebase;
    bool insm = (etot <= ECAP);
    if (insm) {
        for (int i = t; i < etot; i += 128) sidx[i] = d_colA[ebase + i];
    }
    __syncthreads();

    unsigned gb = smem_u32(&gbuf[w][0][0][lane]);   // lane-private 16B slots
    // strides in bytes: buf = 4*32*16 = 2048, slot = 32*16 = 512

#pragma unroll 1
    for (int ii = 0; ii < 8; ii++) {
        int nl = w * 8 + ii;
        int node = node0 + nl;
        float4 a0 = make_float4(0.f, 0.f, 0.f, 0.f), a1 = a0;
        if (node < N_NODES) {
            const int* ip;
            int beg, end;
            if (insm) { ip = sidx;   beg = srow[nl] - ebase; end = srow[nl + 1] - ebase; }
            else      { ip = d_colA; beg = srow[nl];         end = srow[nl + 1]; }
            int nb = (end - beg) >> 2;   // full 4-edge batches

            if (nb > 0) {
#pragma unroll
                for (int s2 = 0; s2 < 4; s2++) {
                    int s = ip[beg + s2];
                    cp_async16(gb + s2 * 512,
                               hin + (size_t)s * HIDDEN + lane * 4);
                }
                CP_COMMIT();
            }
#pragma unroll 1
            for (int b = 0; b < nb; b++) {
                if (b + 1 < nb) {
                    unsigned dstb = gb + ((b + 1) & 1) * 2048;
                    int e2 = beg + (b + 1) * 4;
#pragma unroll
                    for (int s2 = 0; s2 < 4; s2++) {
                        int s = ip[e2 + s2];
                        cp_async16(dstb + s2 * 512,
                                   hin + (size_t)s * HIDDEN + lane * 4);
                    }
                    CP_COMMIT();
                    CP_WAIT1();
                } else {
                    CP_WAIT0();
                }
                float4 v0 = gbuf[w][b & 1][0][lane];
                float4 v1 = gbuf[w][b & 1][1][lane];
                float4 v2 = gbuf[w][b & 1][2][lane];
                float4 v3 = gbuf[w][b & 1][3][lane];
                a0.x += v0.x; a0.y += v0.y; a0.z += v0.z; a0.w += v0.w;
                a1.x += v1.x; a1.y += v1.y; a1.z += v1.z; a1.w += v1.w;
                a0.x += v2.x; a0.y += v2.y; a0.z += v2.z; a0.w += v2.w;
                a1.x += v3.x; a1.y += v3.y; a1.z += v3.z; a1.w += v3.w;
            }
            // tail (0..3 edges): plain register loads
#pragma unroll 1
            for (int j = beg + nb * 4; j < end; j++) {
                int s = ip[j];
                float4 v = ((const float4*)(hin + (size_t)s * HIDDEN))[lane];
                a0.x += v.x; a0.y += v.y; a0.z += v.z; a0.w += v.w;
            }
            float inv = d_deg[node];
            a0.x = (a0.x + a1.x) * inv; a0.y = (a0.y + a1.y) * inv;
            a0.z = (a0.z + a1.z) * inv; a0.w = (a0.w + a1.w) * inv;
        }
        *(float4*)&ms[nl][lane * 4] = a0;
    }
    __syncthreads();

    // Phase 2: (ms @ Wg) — thread (nt=w, ct=lane) owns 8 nodes x 4 cols
    int ct = lane;
    int nt = w;
    int colb = ct * 4;

    u64 acc2[8][2];
#pragma unroll
    for (int i = 0; i < 8; i++) { acc2[i][0] = 0ull; acc2[i][1] = 0ull; }

    const float4* W4 = (const float4*)Wg;
#pragma unroll 4
    for (int k = 0; k < HIDDEN; k++) {
        float4 wv = W4[k * 32 + ct];
        u64 wp0 = pack2(wv.x, wv.y);
        u64 wp1 = pack2(wv.z, wv.w);
#pragma unroll
        for (int i = 0; i < 8; i++) {
            float m = ms[nt * 8 + i][k];
            u64 mp = pack2(m, m);
            fma2(acc2[i][0], mp, wp0);
            fma2(acc2[i][1], mp, wp1);
        }
    }

    float4 bv = ((const float4*)bg)[ct];
    float4 cs = make_float4(0.f, 0.f, 0.f, 0.f);
#pragma unroll
    for (int i = 0; i < 8; i++) {
        int node = node0 + nt * 8 + i;
        if (node < N_NODES) {
            float4 hv = *(const float4*)(hin + (size_t)node * HIDDEN + colb);
            float lo, hi;
            float4 r;
            unpack2(acc2[i][0], lo, hi);
            r.x = fmaxf(hv.x + lo + bv.x, 0.0f);
            r.y = fmaxf(hv.y + hi + bv.y, 0.0f);
            unpack2(acc2[i][1], lo, hi);
            r.z = fmaxf(hv.z + lo + bv.z, 0.0f);
            r.w = fmaxf(hv.w + hi + bv.w, 0.0f);
            *(float4*)(hout + (size_t)node * HIDDEN + colb) = r;
            cs.x += r.x; cs.y += r.y; cs.z += r.z; cs.w += r.w;
        }
    }
    if (do_reduce) {
        atomicAdd(&d_gsum[colb + 0], cs.x);
        atomicAdd(&d_gsum[colb + 1], cs.y);
        atomicAdd(&d_gsum[colb + 2], cs.z);
        atomicAdd(&d_gsum[colb + 3], cs.w);
    }
}

// ---------------------------------------------------------------------------
__global__ void mlp_kernel(const float* __restrict__ W1,
                           const float* __restrict__ b1,
                           const float* __restrict__ W2,
                           const float* __restrict__ b2,
                           float* __restrict__ out) {
    __shared__ float gs[HIDDEN];
    __shared__ float ts[HIDDEN];
    int t = threadIdx.x;  // 256
    if (t < HIDDEN) gs[t] = d_gsum[t] * (1.0f / (float)N_NODES);
    __syncthreads();
    if (t < HIDDEN) {
        float a = b1[t];
#pragma unroll 8
        for (int k = 0; k < HIDDEN; k++) a += gs[k] * W1[k * HIDDEN + t];
        ts[t] = fmaxf(a, 0.0f);
    }
    __syncthreads();
    {
        float a = b2[t];
#pragma unroll 8
        for (int k = 0; k < HIDDEN; k++) a += ts[k] * W2[k * OUT_DIM + t];
        out[t] = a;
    }
}

// ---------------------------------------------------------------------------
extern "C" void kernel_launch(void* const* d_in, const int* in_sizes, int n_in,
                              void* d_out, int out_size) {
    const float* x   = (const float*)d_in[0];
    const int*   src = (const int*)d_in[1];
    const int*   dst = (const int*)d_in[2];
    const float* Wp  = (const float*)d_in[3];
    const float* bp  = (const float*)d_in[4];
    const float* Wg  = (const float*)d_in[5];
    const float* bg  = (const float*)d_in[6];
    const float* W1  = (const float*)d_in[7];
    const float* b1  = (const float*)d_in[8];
    const float* W2  = (const float*)d_in[9];
    const float* b2  = (const float*)d_in[10];
    float* out = (float*)d_out;

    float *h0, *h1;
    cudaGetSymbolAddress((void**)&h0, d_hbuf0);
    cudaGetSymbolAddress((void**)&h1, d_hbuf1);

    const int nblocks = (N_NODES + 31) / 32;   // 1563

    proj_kernel<<<nblocks, 128>>>(x, Wp, bp);
    hist_kernel<<<(N_EDGES + 255) / 256, 256>>>(dst);
    scan_kernel<<<1, 1024>>>();
    fill_kernel<<<(N_EDGES + 255) / 256, 256>>>(src, dst);

    float* bufs[2] = {h0, h1};
    for (int l = 0; l < N_LAYERS; l++) {
        float* hin  = bufs[l & 1];
        float* hout = bufs[(l + 1) & 1];
        layer_kernel<<<nblocks, 128>>>(hin, hout,
                                       Wg + (size_t)l * HIDDEN * HIDDEN,
                                       bg + (size_t)l * HIDDEN,
                                       (l == N_LAYERS - 1) ? 1 : 0);
    }

    mlp_kernel<<<1, 256>>>(W1, b1, W2, b2, out);
}

// round 11
// speedup vs baseline: 1.0475x; 1.0475x over previous
#include <cuda_runtime.h>

#define N_NODES 50000
#define N_EDGES 800000
#define NODE_DIM 64
#define HIDDEN 128
#define OUT_DIM 256
#define N_LAYERS 3
#define ECAP 1024
#define NBLOCKS ((N_NODES + 31) / 32)     // 1563
#define HIST_BLOCKS 1563                  // disjoint blocks appended to proj grid

typedef unsigned long long u64;

// Scratch (static device globals; zero-initialized at load; self-restoring)
__device__ float d_hbuf0[(size_t)N_NODES * HIDDEN];
__device__ float d_hbuf1[(size_t)N_NODES * HIDDEN];
__device__ float d_deg[N_NODES];      // 1/deg (0 for isolated nodes)
__device__ float d_gsum[HIDDEN];      // zeroed by scan_kernel each call
__device__ int   d_cnt[N_NODES];      // histogram; reset by scan_kernel
__device__ int   d_row[N_NODES + 1];  // CSR row offsets
__device__ int   d_cur[N_NODES];      // fill cursors
__device__ int   d_colA[N_EDGES];     // CSR columns (src per edge slot)

// ---- packed f32x2 helpers ---------------------------------------------------
__device__ __forceinline__ u64 pack2(float lo, float hi) {
    u64 r;
    asm("mov.b64 %0, {%1, %2};" : "=l"(r)
        : "r"(__float_as_uint(lo)), "r"(__float_as_uint(hi)));
    return r;
}
__device__ __forceinline__ void unpack2(u64 v, float& lo, float& hi) {
    unsigned int a, b;
    asm("mov.b64 {%0, %1}, %2;" : "=r"(a), "=r"(b) : "l"(v));
    lo = __uint_as_float(a);
    hi = __uint_as_float(b);
}
__device__ __forceinline__ void fma2(u64& acc, u64 a, u64 b) {
    asm("fma.rn.f32x2 %0, %1, %2, %0;" : "+l"(acc) : "l"(a), "l"(b));
}

// ---------------------------------------------------------------------------
// launch 0: proj blocks (0..NBLOCKS-1) compute h0 = x @ Wp + bp;
// hist blocks (NBLOCKS..) histogram dst[] (disjoint code path, same grid).
__global__ void __launch_bounds__(128) proj_hist_kernel(const float* __restrict__ x,
                            const float* __restrict__ Wp,
                            const float* __restrict__ bp,
                            const int* __restrict__ dst) {
    if (blockIdx.x >= NBLOCKS) {
        // histogram path
        int hb = blockIdx.x - NBLOCKS;
        int gt = hb * 128 + threadIdx.x;
        const int nth = HIST_BLOCKS * 128;
#pragma unroll 1
        for (int e = gt; e < N_EDGES; e += nth)
            atomicAdd(&d_cnt[dst[e]], 1);
        return;
    }

    __shared__ float xs[32][NODE_DIM];
    int t = threadIdx.x;
    int node0 = blockIdx.x * 32;

    for (int i = t; i < 32 * (NODE_DIM / 4); i += 128) {
        int r = i >> 4;
        int c4 = i & 15;
        int node = node0 + r;
        float4 v = make_float4(0.f, 0.f, 0.f, 0.f);
        if (node < N_NODES)
            v = ((const float4*)(x + (size_t)node * NODE_DIM))[c4];
        *(float4*)&xs[r][c4 * 4] = v;
    }
    __syncthreads();

    int ct = t & 31;
    int nt = t >> 5;
    int colb = ct * 4;

    u64 acc2[8][2];
#pragma unroll
    for (int i = 0; i < 8; i++) { acc2[i][0] = 0ull; acc2[i][1] = 0ull; }

    const float4* W4 = (const float4*)Wp;
#pragma unroll 4
    for (int k = 0; k < NODE_DIM; k++) {
        float4 w = W4[k * 32 + ct];
        u64 wp0 = pack2(w.x, w.y);
        u64 wp1 = pack2(w.z, w.w);
#pragma unroll
        for (int i = 0; i < 8; i++) {
            float m = xs[nt * 8 + i][k];
            u64 mp = pack2(m, m);
            fma2(acc2[i][0], mp, wp0);
            fma2(acc2[i][1], mp, wp1);
        }
    }

    float4 bv = ((const float4*)bp)[ct];
#pragma unroll
    for (int i = 0; i < 8; i++) {
        int node = node0 + nt * 8 + i;
        if (node < N_NODES) {
            float4 r;
            unpack2(acc2[i][0], r.x, r.y);
            unpack2(acc2[i][1], r.z, r.w);
            r.x += bv.x; r.y += bv.y; r.z += bv.z; r.w += bv.w;
            *(float4*)(d_hbuf0 + (size_t)node * HIDDEN + colb) = r;
        }
    }
}

// ---------------------------------------------------------------------------
// launch 1: single-block scan -> row/cur/deg; resets cnt, gsum.
__global__ void __launch_bounds__(1024) scan_kernel() {
    const int PER = (N_NODES + 1023) / 1024;   // 49
    int t = threadIdx.x;
    int base = t * PER;

    int s = 0;
#pragma unroll 1
    for (int j = 0; j < PER; j++) {
        int i = base + j;
        if (i < N_NODES) s += d_cnt[i];
    }

    int lane = t & 31;
    int wid = t >> 5;
    int incl = s;
#pragma unroll
    for (int off = 1; off < 32; off <<= 1) {
        int v = __shfl_up_sync(0xffffffffu, incl, off);
        if (lane >= off) incl += v;
    }
    __shared__ int wsum[32];
    __shared__ int wpre[32];
    if (lane == 31) wsum[wid] = incl;
    __syncthreads();
    if (wid == 0) {
        int v = wsum[lane];
        int wincl = v;
#pragma unroll
        for (int off = 1; off < 32; off <<= 1) {
            int u2 = __shfl_up_sync(0xffffffffu, wincl, off);
            if (lane >= off) wincl += u2;
        }
        wpre[lane] = wincl - v;
    }
    __syncthreads();

    int run = wpre[wid] + incl - s;
#pragma unroll 1
    for (int j = 0; j < PER; j++) {
        int i = base + j;
        if (i < N_NODES) {
            int c = d_cnt[i];
            d_row[i] = run;
            d_cur[i] = run;
            d_deg[i] = c ? (1.0f / (float)c) : 0.0f;
            d_cnt[i] = 0;
            run += c;
        }
    }
    if (t == 0) d_row[N_NODES] = N_EDGES;
    if (t < HIDDEN) d_gsum[t] = 0.0f;
}

// ---------------------------------------------------------------------------
// launch 2: CSR column fill
__global__ void fill_kernel(const int* __restrict__ src, const int* __restrict__ dst) {
    int e = blockIdx.x * blockDim.x + threadIdx.x;
    if (e < N_EDGES) {
        int d = dst[e];
        int pos = atomicAdd(&d_cur[d], 1);
        d_colA[pos] = src[e];
    }
}

// ---------------------------------------------------------------------------
// launches 3..5: fused GNN layer (R7-proven gather + GEMM) with
// __launch_bounds__(128,7): 72-reg cap -> 7 blocks/SM, 28 warps resident.
// do_reduce: layer 3 accumulates column sums of hout into d_gsum.
__global__ void __launch_bounds__(128, 7) layer_kernel(const float* __restrict__ hin,
                             float* __restrict__ hout,
                             const float* __restrict__ Wg,
                             const float* __restrict__ bg,
                             int do_reduce) {
    __shared__ float ms[32][HIDDEN];   // 16 KB
    __shared__ int sidx[ECAP];         // 4 KB
    __shared__ int srow[33];
    int t = threadIdx.x;
    int node0 = blockIdx.x * 32;
    int lane = t & 31;
    int w = t >> 5;   // warp 0..3

    if (t < 33) srow[t] = d_row[min(node0 + t, N_NODES)];
    __syncthreads();
    int ebase = srow[0];
    int etot = srow[32] - ebase;
    bool insm = (etot <= ECAP);
    if (insm) {
        for (int i = t; i < etot; i += 128) sidx[i] = d_colA[ebase + i];
    }
    __syncthreads();

    // Gather: warp w handles nodes w*8..w*8+7; indices from smem; 8 loads in flight.
#pragma unroll 1
    for (int ii = 0; ii < 8; ii++) {
        int nl = w * 8 + ii;
        int node = node0 + nl;
        float4 a0 = make_float4(0.f, 0.f, 0.f, 0.f), a1 = a0;
        if (node < N_NODES) {
            const int* ip;
            int beg, end;
            if (insm) { ip = sidx;   beg = srow[nl] - ebase; end = srow[nl + 1] - ebase; }
            else      { ip = d_colA; beg = srow[nl];         end = srow[nl + 1]; }
            int j = beg;
#pragma unroll 1
            for (; j + 8 <= end; j += 8) {
                int s0 = ip[j],     s1 = ip[j + 1];
                int s2 = ip[j + 2], s3 = ip[j + 3];
                int s4 = ip[j + 4], s5 = ip[j + 5];
                int s6 = ip[j + 6], s7 = ip[j + 7];
                float4 v0 = ((const float4*)(hin + (size_t)s0 * HIDDEN))[lane];
                float4 v1 = ((const float4*)(hin + (size_t)s1 * HIDDEN))[lane];
                float4 v2 = ((const float4*)(hin + (size_t)s2 * HIDDEN))[lane];
                float4 v3 = ((const float4*)(hin + (size_t)s3 * HIDDEN))[lane];
                float4 v4 = ((const float4*)(hin + (size_t)s4 * HIDDEN))[lane];
                float4 v5 = ((const float4*)(hin + (size_t)s5 * HIDDEN))[lane];
                float4 v6 = ((const float4*)(hin + (size_t)s6 * HIDDEN))[lane];
                float4 v7 = ((const float4*)(hin + (size_t)s7 * HIDDEN))[lane];
                a0.x += v0.x; a0.y += v0.y; a0.z += v0.z; a0.w += v0.w;
                a1.x += v1.x; a1.y += v1.y; a1.z += v1.z; a1.w += v1.w;
                a0.x += v2.x; a0.y += v2.y; a0.z += v2.z; a0.w += v2.w;
                a1.x += v3.x; a1.y += v3.y; a1.z += v3.z; a1.w += v3.w;
                a0.x += v4.x; a0.y += v4.y; a0.z += v4.z; a0.w += v4.w;
                a1.x += v5.x; a1.y += v5.y; a1.z += v5.z; a1.w += v5.w;
                a0.x += v6.x; a0.y += v6.y; a0.z += v6.z; a0.w += v6.w;
                a1.x += v7.x; a1.y += v7.y; a1.z += v7.z; a1.w += v7.w;
            }
            if (j + 4 <= end) {
                int s0 = ip[j], s1 = ip[j + 1], s2 = ip[j + 2], s3 = ip[j + 3];
                float4 v0 = ((const float4*)(hin + (size_t)s0 * HIDDEN))[lane];
                float4 v1 = ((const float4*)(hin + (size_t)s1 * HIDDEN))[lane];
                float4 v2 = ((const float4*)(hin + (size_t)s2 * HIDDEN))[lane];
                float4 v3 = ((const float4*)(hin + (size_t)s3 * HIDDEN))[lane];
                a0.x += v0.x; a0.y += v0.y; a0.z += v0.z; a0.w += v0.w;
                a1.x += v1.x; a1.y += v1.y; a1.z += v1.z; a1.w += v1.w;
                a0.x += v2.x; a0.y += v2.y; a0.z += v2.z; a0.w += v2.w;
                a1.x += v3.x; a1.y += v3.y; a1.z += v3.z; a1.w += v3.w;
                j += 4;
            }
            if (j + 2 <= end) {
                int s0 = ip[j], s1 = ip[j + 1];
                float4 v0 = ((const float4*)(hin + (size_t)s0 * HIDDEN))[lane];
                float4 v1 = ((const float4*)(hin + (size_t)s1 * HIDDEN))[lane];
                a0.x += v0.x; a0.y += v0.y; a0.z += v0.z; a0.w += v0.w;
                a1.x += v1.x; a1.y += v1.y; a1.z += v1.z; a1.w += v1.w;
                j += 2;
            }
            if (j < end) {
                int s = ip[j];
                float4 v = ((const float4*)(hin + (size_t)s * HIDDEN))[lane];
                a0.x += v.x; a0.y += v.y; a0.z += v.z; a0.w += v.w;
            }
            float inv = d_deg[node];
            a0.x = (a0.x + a1.x) * inv; a0.y = (a0.y + a1.y) * inv;
            a0.z = (a0.z + a1.z) * inv; a0.w = (a0.w + a1.w) * inv;
        }
        *(float4*)&ms[nl][lane * 4] = a0;
    }
    __syncthreads();

    // Phase 2: (ms @ Wg) — thread (nt=w, ct=lane) owns 8 nodes x 4 cols
    int ct = lane;
    int nt = w;
    int colb = ct * 4;

    u64 acc2[8][2];
#pragma unroll
    for (int i = 0; i < 8; i++) { acc2[i][0] = 0ull; acc2[i][1] = 0ull; }

    const float4* W4 = (const float4*)Wg;
#pragma unroll 4
    for (int k = 0; k < HIDDEN; k++) {
        float4 wv = W4[k * 32 + ct];
        u64 wp0 = pack2(wv.x, wv.y);
        u64 wp1 = pack2(wv.z, wv.w);
#pragma unroll
        for (int i = 0; i < 8; i++) {
            float m = ms[nt * 8 + i][k];
            u64 mp = pack2(m, m);
            fma2(acc2[i][0], mp, wp0);
            fma2(acc2[i][1], mp, wp1);
        }
    }

    float4 bv = ((const float4*)bg)[ct];
    float4 cs = make_float4(0.f, 0.f, 0.f, 0.f);
#pragma unroll
    for (int i = 0; i < 8; i++) {
        int node = node0 + nt * 8 + i;
        if (node < N_NODES) {
            float4 hv = *(const float4*)(hin + (size_t)node * HIDDEN + colb);
            float lo, hi;
            float4 r;
            unpack2(acc2[i][0], lo, hi);
            r.x = fmaxf(hv.x + lo + bv.x, 0.0f);
            r.y = fmaxf(hv.y + hi + bv.y, 0.0f);
            unpack2(acc2[i][1], lo, hi);
            r.z = fmaxf(hv.z + lo + bv.z, 0.0f);
            r.w = fmaxf(hv.w + hi + bv.w, 0.0f);
            *(float4*)(hout + (size_t)node * HIDDEN + colb) = r;
            cs.x += r.x; cs.y += r.y; cs.z += r.z; cs.w += r.w;
        }
    }
    if (do_reduce) {
        atomicAdd(&d_gsum[colb + 0], cs.x);
        atomicAdd(&d_gsum[colb + 1], cs.y);
        atomicAdd(&d_gsum[colb + 2], cs.z);
        atomicAdd(&d_gsum[colb + 3], cs.w);
    }
}

// ---------------------------------------------------------------------------
__global__ void mlp_kernel(const float* __restrict__ W1,
                           const float* __restrict__ b1,
                           const float* __restrict__ W2,
                           const float* __restrict__ b2,
                           float* __restrict__ out) {
    __shared__ float gs[HIDDEN];
    __shared__ float ts[HIDDEN];
    int t = threadIdx.x;  // 256
    if (t < HIDDEN) gs[t] = d_gsum[t] * (1.0f / (float)N_NODES);
    __syncthreads();
    if (t < HIDDEN) {
        float a = b1[t];
#pragma unroll 8
        for (int k = 0; k < HIDDEN; k++) a += gs[k] * W1[k * HIDDEN + t];
        ts[t] = fmaxf(a, 0.0f);
    }
    __syncthreads();
    {
        float a = b2[t];
#pragma unroll 8
        for (int k = 0; k < HIDDEN; k++) a += ts[k] * W2[k * OUT_DIM + t];
        out[t] = a;
    }
}

// ---------------------------------------------------------------------------
extern "C" void kernel_launch(void* const* d_in, const int* in_sizes, int n_in,
                              void* d_out, int out_size) {
    const float* x   = (const float*)d_in[0];
    const int*   src = (const int*)d_in[1];
    const int*   dst = (const int*)d_in[2];
    const float* Wp  = (const float*)d_in[3];
    const float* bp  = (const float*)d_in[4];
    const float* Wg  = (const float*)d_in[5];
    const float* bg  = (const float*)d_in[6];
    const float* W1  = (const float*)d_in[7];
    const float* b1  = (const float*)d_in[8];
    const float* W2  = (const float*)d_in[9];
    const float* b2  = (const float*)d_in[10];
    float* out = (float*)d_out;

    float *h0, *h1;
    cudaGetSymbolAddress((void**)&h0, d_hbuf0);
    cudaGetSymbolAddress((void**)&h1, d_hbuf1);

    // launch 0: proj + hist (disjoint block ranges)
    proj_hist_kernel<<<NBLOCKS + HIST_BLOCKS, 128>>>(x, Wp, bp, dst);
    // launch 1: scan (row/cur/deg; resets cnt, gsum)
    scan_kernel<<<1, 1024>>>();
    // launch 2: CSR fill
    fill_kernel<<<(N_EDGES + 255) / 256, 256>>>(src, dst);

    // launches 3..5: GNN layers (ping-pong); layer 3 fuses the column reduce
    float* bufs[2] = {h0, h1};
    for (int l = 0; l < N_LAYERS; l++) {
        float* hin  = bufs[l & 1];
        float* hout = bufs[(l + 1) & 1];
        layer_kernel<<<NBLOCKS, 128>>>(hin, hout,
                                       Wg + (size_t)l * HIDDEN * HIDDEN,
                                       bg + (size_t)l * HIDDEN,
                                       (l == N_LAYERS - 1) ? 1 : 0);
    }

    // launch 6: MLP head
    mlp_kernel<<<1, 256>>>(W1, b1, W2, b2, out);
}

// round 12
// speedup vs baseline: 1.4190x; 1.3546x over previous
#include <cuda_runtime.h>

#define N_NODES 50000
#define N_EDGES 800000
#define NODE_DIM 64
#define HIDDEN 128
#define OUT_DIM 256
#define N_LAYERS 3
#define ECAP 1024
#define SCAN_BLOCKS ((N_NODES + 255) / 256)   // 196

typedef unsigned long long u64;

// Scratch (static device globals; zero-initialized at load; self-restoring)
__device__ float d_hbuf0[(size_t)N_NODES * HIDDEN];
__device__ float d_hbuf1[(size_t)N_NODES * HIDDEN];
__device__ float d_deg[N_NODES];      // 1/deg (0 for isolated nodes)
__device__ float d_gsum[HIDDEN];      // zeroed by scan3 each call
__device__ int   d_cnt[N_NODES];      // histogram; reset by scan3
__device__ int   d_row[N_NODES + 1];  // CSR row offsets
__device__ int   d_cur[N_NODES];      // fill cursors
__device__ int   d_colA[N_EDGES];     // CSR columns (src per edge slot)
__device__ int   d_bsum[SCAN_BLOCKS];

// ---- packed f32x2 helpers ---------------------------------------------------
__device__ __forceinline__ u64 pack2(float lo, float hi) {
    u64 r;
    asm("mov.b64 %0, {%1, %2};" : "=l"(r)
        : "r"(__float_as_uint(lo)), "r"(__float_as_uint(hi)));
    return r;
}
__device__ __forceinline__ void unpack2(u64 v, float& lo, float& hi) {
    unsigned int a, b;
    asm("mov.b64 {%0, %1}, %2;" : "=r"(a), "=r"(b) : "l"(v));
    lo = __uint_as_float(a);
    hi = __uint_as_float(b);
}
__device__ __forceinline__ void fma2(u64& acc, u64 a, u64 b) {
    asm("fma.rn.f32x2 %0, %1, %2, %0;" : "+l"(acc) : "l"(a), "l"(b));
}

// ---------------------------------------------------------------------------
// launch 0: h0 = x @ Wp + bp   (R4-proven)
__global__ void __launch_bounds__(128) proj_kernel(const float* __restrict__ x,
                            const float* __restrict__ Wp,
                            const float* __restrict__ bp) {
    __shared__ float xs[32][NODE_DIM];
    int t = threadIdx.x;
    int node0 = blockIdx.x * 32;

    for (int i = t; i < 32 * (NODE_DIM / 4); i += 128) {
        int r = i >> 4;
        int c4 = i & 15;
        int node = node0 + r;
        float4 v = make_float4(0.f, 0.f, 0.f, 0.f);
        if (node < N_NODES)
            v = ((const float4*)(x + (size_t)node * NODE_DIM))[c4];
        *(float4*)&xs[r][c4 * 4] = v;
    }
    __syncthreads();

    int ct = t & 31;
    int nt = t >> 5;
    int colb = ct * 4;

    u64 acc2[8][2];
#pragma unroll
    for (int i = 0; i < 8; i++) { acc2[i][0] = 0ull; acc2[i][1] = 0ull; }

    const float4* W4 = (const float4*)Wp;
#pragma unroll 4
    for (int k = 0; k < NODE_DIM; k++) {
        float4 w = W4[k * 32 + ct];
        u64 wp0 = pack2(w.x, w.y);
        u64 wp1 = pack2(w.z, w.w);
#pragma unroll
        for (int i = 0; i < 8; i++) {
            float m = xs[nt * 8 + i][k];
            u64 mp = pack2(m, m);
            fma2(acc2[i][0], mp, wp0);
            fma2(acc2[i][1], mp, wp1);
        }
    }

    float4 bv = ((const float4*)bp)[ct];
#pragma unroll
    for (int i = 0; i < 8; i++) {
        int node = node0 + nt * 8 + i;
        if (node < N_NODES) {
            float4 r;
            unpack2(acc2[i][0], r.x, r.y);
            unpack2(acc2[i][1], r.z, r.w);
            r.x += bv.x; r.y += bv.y; r.z += bv.z; r.w += bv.w;
            *(float4*)(d_hbuf0 + (size_t)node * HIDDEN + colb) = r;
        }
    }
}

// ---------------------------------------------------------------------------
// launch 1: degree histogram (d_cnt zero at entry; scan3 resets it each call)
__global__ void hist_kernel(const int* __restrict__ dst) {
    int e = blockIdx.x * blockDim.x + threadIdx.x;
    if (e < N_EDGES) atomicAdd(&d_cnt[dst[e]], 1);
}

// launch 2: block-level exclusive scan of d_cnt (R4-proven)
__global__ void scan1_kernel() {
    __shared__ int sd[256];
    int t = threadIdx.x;
    int i = blockIdx.x * 256 + t;
    int v = (i < N_NODES) ? d_cnt[i] : 0;
    sd[t] = v;
    __syncthreads();
#pragma unroll
    for (int off = 1; off < 256; off <<= 1) {
        int a = (t >= off) ? sd[t - off] : 0;
        __syncthreads();
        sd[t] += a;
        __syncthreads();
    }
    if (i < N_NODES) d_row[i] = sd[t] - v;   // exclusive within block
    if (t == 255) d_bsum[blockIdx.x] = sd[t];
}

// launch 3: scan of block sums (R4-proven)
__global__ void scan2_kernel() {
    __shared__ int sd[256];
    int t = threadIdx.x;
    int v = (t < SCAN_BLOCKS) ? d_bsum[t] : 0;
    sd[t] = v;
    __syncthreads();
#pragma unroll
    for (int off = 1; off < 256; off <<= 1) {
        int a = (t >= off) ? sd[t - off] : 0;
        __syncthreads();
        sd[t] += a;
        __syncthreads();
    }
    if (t < SCAN_BLOCKS) d_bsum[t] = sd[t] - v;  // exclusive
}

// launch 4: finish row offsets, cursors, 1/deg; self-reset cnt + gsum.
__global__ void scan3_kernel() {
    int i = blockIdx.x * blockDim.x + threadIdx.x;
    if (i < N_NODES) {
        int r = d_row[i] + d_bsum[blockIdx.x];
        d_row[i] = r;
        d_cur[i] = r;
        int c = d_cnt[i];
        d_deg[i] = (c > 0) ? (1.0f / (float)c) : 0.0f;
        d_cnt[i] = 0;                  // ready for next replay
    }
    if (i == 0) d_row[N_NODES] = N_EDGES;
    if (i < HIDDEN) d_gsum[i] = 0.0f;  // reset before layer-3 accumulates
}

// launch 5: CSR column fill
__global__ void fill_kernel(const int* __restrict__ src, const int* __restrict__ dst) {
    int e = blockIdx.x * blockDim.x + threadIdx.x;
    if (e < N_EDGES) {
        int d = dst[e];
        int pos = atomicAdd(&d_cur[d], 1);
        d_colA[pos] = src[e];
    }
}

// ---------------------------------------------------------------------------
// launches 6..8: fused GNN layer: hout = relu(hin + gather_mean(hin) @ Wg + bg)
// Gather: R7-proven (smem idx prefetch, 8 row-LDG.128 in flight, NO regcap).
// GEMM: R4-proven packed fma2, thread owns 8 nodes x 4 cols.
// do_reduce (layer 3): column sums of hout into d_gsum (R6-verified neutral).
__global__ void __launch_bounds__(128) layer_kernel(const float* __restrict__ hin,
                             float* __restrict__ hout,
                             const float* __restrict__ Wg,
                             const float* __restrict__ bg,
                             int do_reduce) {
    __shared__ float ms[32][HIDDEN];   // 16 KB
    __shared__ int sidx[ECAP];         // 4 KB
    __shared__ int srow[33];
    int t = threadIdx.x;
    int node0 = blockIdx.x * 32;
    int lane = t & 31;
    int w = t >> 5;   // warp 0..3

    if (t < 33) srow[t] = d_row[min(node0 + t, N_NODES)];
    __syncthreads();
    int ebase = srow[0];
    int etot = srow[32] - ebase;
    bool insm = (etot <= ECAP);
    if (insm) {
        for (int i = t; i < etot; i += 128) sidx[i] = d_colA[ebase + i];
    }
    __syncthreads();

#pragma unroll 1
    for (int ii = 0; ii < 8; ii++) {
        int nl = w * 8 + ii;
        int node = node0 + nl;
        float4 a0 = make_float4(0.f, 0.f, 0.f, 0.f), a1 = a0;
        if (node < N_NODES) {
            const int* ip;
            int beg, end;
            if (insm) { ip = sidx;   beg = srow[nl] - ebase; end = srow[nl + 1] - ebase; }
            else      { ip = d_colA; beg = srow[nl];         end = srow[nl + 1]; }
            int j = beg;
#pragma unroll 1
            for (; j + 8 <= end; j += 8) {
                int s0 = ip[j],     s1 = ip[j + 1];
                int s2 = ip[j + 2], s3 = ip[j + 3];
                int s4 = ip[j + 4], s5 = ip[j + 5];
                int s6 = ip[j + 6], s7 = ip[j + 7];
                float4 v0 = ((const float4*)(hin + (size_t)s0 * HIDDEN))[lane];
                float4 v1 = ((const float4*)(hin + (size_t)s1 * HIDDEN))[lane];
                float4 v2 = ((const float4*)(hin + (size_t)s2 * HIDDEN))[lane];
                float4 v3 = ((const float4*)(hin + (size_t)s3 * HIDDEN))[lane];
                float4 v4 = ((const float4*)(hin + (size_t)s4 * HIDDEN))[lane];
                float4 v5 = ((const float4*)(hin + (size_t)s5 * HIDDEN))[lane];
                float4 v6 = ((const float4*)(hin + (size_t)s6 * HIDDEN))[lane];
                float4 v7 = ((const float4*)(hin + (size_t)s7 * HIDDEN))[lane];
                a0.x += v0.x; a0.y += v0.y; a0.z += v0.z; a0.w += v0.w;
                a1.x += v1.x; a1.y += v1.y; a1.z += v1.z; a1.w += v1.w;
                a0.x += v2.x; a0.y += v2.y; a0.z += v2.z; a0.w += v2.w;
                a1.x += v3.x; a1.y += v3.y; a1.z += v3.z; a1.w += v3.w;
                a0.x += v4.x; a0.y += v4.y; a0.z += v4.z; a0.w += v4.w;
                a1.x += v5.x; a1.y += v5.y; a1.z += v5.z; a1.w += v5.w;
                a0.x += v6.x; a0.y += v6.y; a0.z += v6.z; a0.w += v6.w;
                a1.x += v7.x; a1.y += v7.y; a1.z += v7.z; a1.w += v7.w;
            }
            if (j + 4 <= end) {
                int s0 = ip[j], s1 = ip[j + 1], s2 = ip[j + 2], s3 = ip[j + 3];
                float4 v0 = ((const float4*)(hin + (size_t)s0 * HIDDEN))[lane];
                float4 v1 = ((const float4*)(hin + (size_t)s1 * HIDDEN))[lane];
                float4 v2 = ((const float4*)(hin + (size_t)s2 * HIDDEN))[lane];
                float4 v3 = ((const float4*)(hin + (size_t)s3 * HIDDEN))[lane];
                a0.x += v0.x; a0.y += v0.y; a0.z += v0.z; a0.w += v0.w;
                a1.x += v1.x; a1.y += v1.y; a1.z += v1.z; a1.w += v1.w;
                a0.x += v2.x; a0.y += v2.y; a0.z += v2.z; a0.w += v2.w;
                a1.x += v3.x; a1.y += v3.y; a1.z += v3.z; a1.w += v3.w;
                j += 4;
            }
            if (j + 2 <= end) {
                int s0 = ip[j], s1 = ip[j + 1];
                float4 v0 = ((const float4*)(hin + (size_t)s0 * HIDDEN))[lane];
                float4 v1 = ((const float4*)(hin + (size_t)s1 * HIDDEN))[lane];
                a0.x += v0.x; a0.y += v0.y; a0.z += v0.z; a0.w += v0.w;
                a1.x += v1.x; a1.y += v1.y; a1.z += v1.z; a1.w += v1.w;
                j += 2;
            }
            if (j < end) {
                int s = ip[j];
                float4 v = ((const float4*)(hin + (size_t)s * HIDDEN))[lane];
                a0.x += v.x; a0.y += v.y; a0.z += v.z; a0.w += v.w;
            }
            float inv = d_deg[node];
            a0.x = (a0.x + a1.x) * inv; a0.y = (a0.y + a1.y) * inv;
            a0.z = (a0.z + a1.z) * inv; a0.w = (a0.w + a1.w) * inv;
        }
        *(float4*)&ms[nl][lane * 4] = a0;
    }
    __syncthreads();

    // Phase 2: (ms @ Wg)
    int ct = lane;
    int nt = w;
    int colb = ct * 4;

    u64 acc2[8][2];
#pragma unroll
    for (int i = 0; i < 8; i++) { acc2[i][0] = 0ull; acc2[i][1] = 0ull; }

    const float4* W4 = (const float4*)Wg;
#pragma unroll 4
    for (int k = 0; k < HIDDEN; k++) {
        float4 wv = W4[k * 32 + ct];
        u64 wp0 = pack2(wv.x, wv.y);
        u64 wp1 = pack2(wv.z, wv.w);
#pragma unroll
        for (int i = 0; i < 8; i++) {
            float m = ms[nt * 8 + i][k];
            u64 mp = pack2(m, m);
            fma2(acc2[i][0], mp, wp0);
            fma2(acc2[i][1], mp, wp1);
        }
    }

    float4 bv = ((const float4*)bg)[ct];
    float4 cs = make_float4(0.f, 0.f, 0.f, 0.f);
#pragma unroll
    for (int i = 0; i < 8; i++) {
        int node = node0 + nt * 8 + i;
        if (node < N_NODES) {
            float4 hv = *(const float4*)(hin + (size_t)node * HIDDEN + colb);
            float lo, hi;
            float4 r;
            unpack2(acc2[i][0], lo, hi);
            r.x = fmaxf(hv.x + lo + bv.x, 0.0f);
            r.y = fmaxf(hv.y + hi + bv.y, 0.0f);
            unpack2(acc2[i][1], lo, hi);
            r.z = fmaxf(hv.z + lo + bv.z, 0.0f);
            r.w = fmaxf(hv.w + hi + bv.w, 0.0f);
            *(float4*)(hout + (size_t)node * HIDDEN + colb) = r;
            cs.x += r.x; cs.y += r.y; cs.z += r.z; cs.w += r.w;
        }
    }
    if (do_reduce) {
        atomicAdd(&d_gsum[colb + 0], cs.x);
        atomicAdd(&d_gsum[colb + 1], cs.y);
        atomicAdd(&d_gsum[colb + 2], cs.z);
        atomicAdd(&d_gsum[colb + 3], cs.w);
    }
}

// ---------------------------------------------------------------------------
__global__ void mlp_kernel(const float* __restrict__ W1,
                           const float* __restrict__ b1,
                           const float* __restrict__ W2,
                           const float* __restrict__ b2,
                           float* __restrict__ out) {
    __shared__ float gs[HIDDEN];
    __shared__ float ts[HIDDEN];
    int t = threadIdx.x;  // 256
    if (t < HIDDEN) gs[t] = d_gsum[t] * (1.0f / (float)N_NODES);
    __syncthreads();
    if (t < HIDDEN) {
        float a = b1[t];
#pragma unroll 8
        for (int k = 0; k < HIDDEN; k++) a += gs[k] * W1[k * HIDDEN + t];
        ts[t] = fmaxf(a, 0.0f);
    }
    __syncthreads();
    {
        float a = b2[t];
#pragma unroll 8
        for (int k = 0; k < HIDDEN; k++) a += ts[k] * W2[k * OUT_DIM + t];
        out[t] = a;
    }
}

// ---------------------------------------------------------------------------
extern "C" void kernel_launch(void* const* d_in, const int* in_sizes, int n_in,
                              void* d_out, int out_size) {
    const float* x   = (const float*)d_in[0];
    const int*   src = (const int*)d_in[1];
    const int*   dst = (const int*)d_in[2];
    const float* Wp  = (const float*)d_in[3];
    const float* bp  = (const float*)d_in[4];
    const float* Wg  = (const float*)d_in[5];
    const float* bg  = (const float*)d_in[6];
    const float* W1  = (const float*)d_in[7];
    const float* b1  = (const float*)d_in[8];
    const float* W2  = (const float*)d_in[9];
    const float* b2  = (const float*)d_in[10];
    float* out = (float*)d_out;

    float *h0, *h1;
    cudaGetSymbolAddress((void**)&h0, d_hbuf0);
    cudaGetSymbolAddress((void**)&h1, d_hbuf1);

    const int nblocks = (N_NODES + 31) / 32;   // 1563

    proj_kernel<<<nblocks, 128>>>(x, Wp, bp);
    hist_kernel<<<(N_EDGES + 255) / 256, 256>>>(dst);
    scan1_kernel<<<SCAN_BLOCKS, 256>>>();
    scan2_kernel<<<1, 256>>>();
    scan3_kernel<<<SCAN_BLOCKS, 256>>>();
    fill_kernel<<<(N_EDGES + 255) / 256, 256>>>(src, dst);

    float* bufs[2] = {h0, h1};
    for (int l = 0; l < N_LAYERS; l++) {
        float* hin  = bufs[l & 1];
        float* hout = bufs[(l + 1) & 1];
        layer_kernel<<<nblocks, 128>>>(hin, hout,
                                       Wg + (size_t)l * HIDDEN * HIDDEN,
                                       bg + (size_t)l * HIDDEN,
                                       (l == N_LAYERS - 1) ? 1 : 0);
    }

    mlp_kernel<<<1, 256>>>(W1, b1, W2, b2, out);
}